// round 7
// baseline (speedup 1.0000x reference)
#include <cuda_runtime.h>
#include <cuda_bf16.h>

#define BX    32
#define BY    4
#define IND   384
#define OUTD  377
#define BATCH 32
#define NT    128
#define SP    65            // Osh4 pixel-dim stride (f4 units), 2 rows + pad

// D[k][n] = 2*cos(pi*k*(2n+1)/14), compile-time constants -> FFMA-imm
__device__ static constexpr float DC[7][7] = {
  { 2.0f, 2.0f, 2.0f, 2.0f, 2.0f, 2.0f, 2.0f },
  { 1.9498558243636472f,  1.5636629649360596f,  0.8677674782351162f, 0.0f,
   -0.8677674782351162f, -1.5636629649360596f, -1.9498558243636472f },
  { 1.8019377358048383f,  0.4450418679126288f, -1.2469796037174672f, -2.0f,
   -1.2469796037174672f,  0.4450418679126288f,  1.8019377358048383f },
  { 1.5636629649360596f, -0.8677674782351162f, -1.9498558243636472f, 0.0f,
    1.9498558243636472f,  0.8677674782351162f, -1.5636629649360596f },
  { 1.2469796037174672f, -1.8019377358048383f, -0.4450418679126288f, 2.0f,
   -0.4450418679126288f, -1.8019377358048383f,  1.2469796037174672f },
  { 0.8677674782351162f, -1.9498558243636472f,  1.5636629649360596f, 0.0f,
   -1.5636629649360596f,  1.9498558243636472f, -0.8677674782351162f },
  { 0.4450418679126288f, -1.2469796037174672f,  1.8019377358048383f, -2.0f,
    1.8019377358048383f, -1.2469796037174672f,  0.4450418679126288f }
};

__device__ __forceinline__ void vert7(const float x[7], float Vk[7])
{
    float sx[3], dx[3];
    #pragma unroll
    for (int m = 0; m < 3; m++) { sx[m] = x[m] + x[6 - m]; dx[m] = x[m] - x[6 - m]; }
    #pragma unroll
    for (int k = 0; k < 7; k++) {
        float s;
        if ((k & 1) == 0) {
            s = DC[k][3] * x[3];
            #pragma unroll
            for (int m = 0; m < 3; m++) s = fmaf(DC[k][m], sx[m], s);
        } else {
            s = DC[k][0] * dx[0];
            s = fmaf(DC[k][1], dx[1], s);
            s = fmaf(DC[k][2], dx[2], s);
        }
        Vk[k] = s;
    }
}

__global__ __launch_bounds__(NT, 10)
void dct_conv_kernel(const float* __restrict__ X, float* __restrict__ out)
{
    __shared__ float4 Osh4[12 * SP];     // hf staging for a 2-row group

    const int tid  = threadIdx.x;
    const int w    = tid >> 5;           // warp = output row within tile
    const int lane = tid & 31;           // lane = column within tile
    const int x0   = blockIdx.x * BX;
    const int y0   = blockIdx.y * BY;
    const int b    = blockIdx.z;

    const int nvx = min(BX, OUTD - x0);
    const long long ZF = (long long)BATCH * OUTD * OUTD;

    // ---- per-warp vertical DCT, register-resident (no smem) ----
    float Vk0[7], Vk1[7];
    {
        const float* Xb = X + (size_t)b * IND * IND;
        const int gy  = y0 + w;              // top row of this warp's window
        const int gx0 = x0 + lane;           // always < IND (352+31=383)
        const int gx1 = x0 + 32 + lane;      // halo cols, lanes 0..5 only
        const bool h_ok = (lane < 6) && (gx1 < IND);
        float c0[7], c1[7];
        #pragma unroll
        for (int m = 0; m < 7; m++) {
            int  gr = gy + m;
            bool rv = gr < IND;
            const float* rowp = Xb + (size_t)gr * IND;
            c0[m] = rv          ? __ldg(rowp + gx0) : 0.0f;
            c1[m] = (rv && h_ok) ? __ldg(rowp + gx1) : 0.0f;
        }
        vert7(c0, Vk0);
        vert7(c1, Vk1);
    }

    // ---- horizontal pass: shuffle-based neighbor gather, stage to Osh4 ----
    auto horiz = [&](int slot) {
        float b0 = 0.f, b1 = 0.f, b2 = 0.f;
        const int sbase = slot * 32 + lane;
        #pragma unroll
        for (int k = 0; k < 7; k++) {
            float v[7];
            v[0] = Vk0[k];
            #pragma unroll
            for (int n = 1; n < 7; n++) {
                float s0 = __shfl_down_sync(0xffffffffu, Vk0[k], n);
                float s1 = __shfl_sync(0xffffffffu, Vk1[k], lane + n); // wraps mod 32
                v[n] = (lane < 32 - n) ? s0 : s1;
            }
            float sv[3], dv[3];
            #pragma unroll
            for (int n = 0; n < 3; n++) { sv[n] = v[n] + v[6 - n]; dv[n] = v[n] - v[6 - n]; }

            #pragma unroll
            for (int i = 0; i < 7; i++) {
                float a;
                if ((i & 1) == 0) {
                    a = DC[i][3] * v[3];
                    #pragma unroll
                    for (int n = 0; n < 3; n++) a = fmaf(DC[i][n], sv[n], a);
                } else {
                    a = DC[i][0] * dv[0];
                    a = fmaf(DC[i][1], dv[1], a);
                    a = fmaf(DC[i][2], dv[2], a);
                }

                const int ch = k * 7 + i;            // compile-time constant
                if (ch == 0) {
                    int x = x0 + lane, y = y0 + w;
                    if (x < OUTD && y < OUTD)
                        __stcs(&out[((size_t)b * OUTD + y) * OUTD + x], a);
                } else {
                    const int pos = (ch - 1) & 3;    // compile-time constant
                    if      (pos == 0) b0 = a;
                    else if (pos == 1) b1 = a;
                    else if (pos == 2) b2 = a;
                    else Osh4[((ch - 4) >> 2) * SP + sbase] = make_float4(b0, b1, b2, a);
                }
            }
        }
    };

    // ---- drain one 2-row group: contiguous STG.128 per row ----
    auto drain = [&](int phase) {
        #pragma unroll
        for (int j = 0; j < 6; j++) {
            int g  = tid + j * NT;        // 0..767
            int rr = g / 384;
            int h  = g - rr * 384;
            int pl = h / 12;
            int c  = h - pl * 12;
            int y  = y0 + phase * 2 + rr;
            if (y < OUTD && pl < nvx) {
                float4* dst = (float4*)(out + ZF +
                              (((size_t)b * OUTD + y) * OUTD + x0) * 48);
                __stcs(&dst[pl * 12 + c], Osh4[c * SP + rr * 32 + pl]);
            }
        }
    };

    // phase 0: warps 0,1 stage rows 0,1 (all warps already hold V in regs)
    if (w < 2) horiz(w);
    __syncthreads();
    drain(0);
    __syncthreads();

    // phase 1: warps 2,3 stage rows 2,3
    if (w >= 2) horiz(w - 2);
    __syncthreads();
    drain(1);
}

extern "C" void kernel_launch(void* const* d_in, const int* in_sizes, int n_in,
                              void* d_out, int out_size)
{
    const float* X = (const float*)d_in[0];
    float* out = (float*)d_out;

    dim3 grid((OUTD + BX - 1) / BX,   // 12
              (OUTD + BY - 1) / BY,   // 95
              BATCH);                 // 32
    dct_conv_kernel<<<grid, NT>>>(X, out);
}

// round 9
// speedup vs baseline: 1.0880x; 1.0880x over previous
#include <cuda_runtime.h>
#include <cuda_bf16.h>

#define BX    32
#define BY    4
#define TX    38            // BX + 6
#define TYR   10            // BY + 6
#define IND   384
#define OUTD  377
#define BATCH 32
#define NT    128

// Staging: 2 row slots x 16 chunks x (2px*12 f4 + 1 f4 pad) = 2 x 400 f4
#define CHUNK_F4 25          // 24 f4 payload (2 px) + 1 f4 pad -> stride 400B

// D[k][n] = 2*cos(pi*k*(2n+1)/14), compile-time constants -> FFMA-imm
__device__ static constexpr float DC[7][7] = {
  { 2.0f, 2.0f, 2.0f, 2.0f, 2.0f, 2.0f, 2.0f },
  { 1.9498558243636472f,  1.5636629649360596f,  0.8677674782351162f, 0.0f,
   -0.8677674782351162f, -1.5636629649360596f, -1.9498558243636472f },
  { 1.8019377358048383f,  0.4450418679126288f, -1.2469796037174672f, -2.0f,
   -1.2469796037174672f,  0.4450418679126288f,  1.8019377358048383f },
  { 1.5636629649360596f, -0.8677674782351162f, -1.9498558243636472f, 0.0f,
    1.9498558243636472f,  0.8677674782351162f, -1.5636629649360596f },
  { 1.2469796037174672f, -1.8019377358048383f, -0.4450418679126288f, 2.0f,
   -0.4450418679126288f, -1.8019377358048383f,  1.2469796037174672f },
  { 0.8677674782351162f, -1.9498558243636472f,  1.5636629649360596f, 0.0f,
   -1.5636629649360596f,  1.9498558243636472f, -0.8677674782351162f },
  { 0.4450418679126288f, -1.2469796037174672f,  1.8019377358048383f, -2.0f,
    1.8019377358048383f, -1.2469796037174672f,  0.4450418679126288f }
};

__global__ __launch_bounds__(NT, 9)
void dct_conv_kernel(const float* __restrict__ X, float* __restrict__ out)
{
    __shared__ float  Xs[TYR][TX];            // input tile
    __shared__ float  Vs[7][BY][TX];          // vertical DCT pass
    __shared__ float4 Osh4[2][16 * CHUNK_F4]; // pixel-major staging, 2 rows

    const int tid  = threadIdx.x;
    const int w    = tid >> 5;
    const int lane = tid & 31;
    const int x0   = blockIdx.x * BX;
    const int y0   = blockIdx.y * BY;
    const int b    = blockIdx.z;

    const int nvx     = min(BX, OUTD - x0);
    const int nchunks = (nvx + 1) >> 1;         // 16 or 13
    const long long ZF = (long long)BATCH * OUTD * OUTD;

    // ---- stage input tile (clamped; OOB values only feed invalid pixels) ----
    const float* Xb = X + (size_t)b * IND * IND;
    #pragma unroll
    for (int i = tid; i < TYR * TX; i += NT) {
        int r  = i / TX, c = i - r * TX;
        int gr = y0 + r, gc = x0 + c;
        Xs[r][c] = (gr < IND && gc < IND) ? __ldg(Xb + gr * IND + gc) : 0.0f;
    }
    __syncthreads();

    // ---- vertical pass (butterfly + immediate coefficients) ----
    for (int i = tid; i < BY * TX; i += NT) {
        int ty = i / TX, xx = i - ty * TX;
        float x[7];
        #pragma unroll
        for (int m = 0; m < 7; m++) x[m] = Xs[ty + m][xx];
        float sx[3], dx[3];
        #pragma unroll
        for (int m = 0; m < 3; m++) { sx[m] = x[m] + x[6 - m]; dx[m] = x[m] - x[6 - m]; }

        #pragma unroll
        for (int k = 0; k < 7; k++) {
            float s;
            if ((k & 1) == 0) {
                s = DC[k][3] * x[3];
                #pragma unroll
                for (int m = 0; m < 3; m++) s = fmaf(DC[k][m], sx[m], s);
            } else {
                s = DC[k][0] * dx[0];
                s = fmaf(DC[k][1], dx[1], s);
                s = fmaf(DC[k][2], dx[2], s);
            }
            Vs[k][ty][xx] = s;
        }
    }
    __syncthreads();

    // ---- horizontal pass: lane = pixel; pixel-major chunked staging ----
    // chunk q = lane>>1 (2 px), r = lane&1; f4 addr = q*25 + r*12 + c
    // -> word bank = (4q + 16r + 4c) % 32 : conflict-free per 8-lane phase.
    auto horiz = [&](int row, int slot) {
        float4* dst = &Osh4[slot][(lane >> 1) * CHUNK_F4 + (lane & 1) * 12];
        float b0 = 0.f, b1 = 0.f, b2 = 0.f;
        #pragma unroll
        for (int k = 0; k < 7; k++) {
            float v[7];
            #pragma unroll
            for (int n = 0; n < 7; n++) v[n] = Vs[k][row][lane + n];
            float sv[3], dv[3];
            #pragma unroll
            for (int n = 0; n < 3; n++) { sv[n] = v[n] + v[6 - n]; dv[n] = v[n] - v[6 - n]; }

            #pragma unroll
            for (int i = 0; i < 7; i++) {
                float a;
                if ((i & 1) == 0) {
                    a = DC[i][3] * v[3];
                    #pragma unroll
                    for (int n = 0; n < 3; n++) a = fmaf(DC[i][n], sv[n], a);
                } else {
                    a = DC[i][0] * dv[0];
                    a = fmaf(DC[i][1], dv[1], a);
                    a = fmaf(DC[i][2], dv[2], a);
                }

                const int ch = k * 7 + i;            // compile-time constant
                if (ch == 0) {
                    int x = x0 + lane, y = y0 + row;
                    if (x < OUTD && y < OUTD)
                        __stcs(&out[((size_t)b * OUTD + y) * OUTD + x], a);
                } else {
                    const int pos = (ch - 1) & 3;    // compile-time constant
                    if      (pos == 0) b0 = a;
                    else if (pos == 1) b1 = a;
                    else if (pos == 2) b2 = a;
                    else dst[(ch - 4) >> 2] = make_float4(b0, b1, b2, a);
                }
            }
        }
    };

    // ---- TMA bulk writeout of one 2-row phase (threads 0..63) ----
    // thread t: row slot rr = t>>5, chunk j = t&31. One 384B (or 192B) cmd.
    auto issue = [&](int phase) {
        if (tid < 64) {
            int rr  = tid >> 5;
            int j   = tid & 31;
            int y   = y0 + phase * 2 + rr;
            if (y < OUTD && j < nchunks) {
                int sz = ((j == nchunks - 1) && (nvx & 1)) ? 192 : 384;
                const float* gp = out + ZF +
                    (((size_t)b * OUTD + y) * OUTD + x0 + 2 * j) * 48;
                unsigned long long gaddr =
                    (unsigned long long)__cvta_generic_to_global((void*)gp);
                unsigned int saddr = (unsigned int)__cvta_generic_to_shared(
                    &Osh4[rr][j * CHUNK_F4]);
                asm volatile("fence.proxy.async.shared::cta;" ::: "memory");
                asm volatile(
                    "cp.async.bulk.global.shared::cta.bulk_group [%0], [%1], %2;"
                    :: "l"(gaddr), "r"(saddr), "r"(sz) : "memory");
                asm volatile("cp.async.bulk.commit_group;" ::: "memory");
            }
        }
    };

    // phase 0: warps 0,1 compute+stage rows 0,1 (row = w, slot = w)
    if (w < 2) horiz(w, w);
    __syncthreads();
    issue(0);
    // wait for phase-0 bulk reads before warps 2,3 overwrite the buffer
    if (tid < 64)
        asm volatile("cp.async.bulk.wait_group 0;" ::: "memory");
    __syncthreads();

    // phase 1: warps 2,3 compute+stage rows 2,3 (row = w, slot = w-2)
    if (w >= 2) horiz(w, w - 2);
    __syncthreads();
    issue(1);
    if (tid < 64)
        asm volatile("cp.async.bulk.wait_group 0;" ::: "memory");
}

extern "C" void kernel_launch(void* const* d_in, const int* in_sizes, int n_in,
                              void* d_out, int out_size)
{
    const float* X = (const float*)d_in[0];
    float* out = (float*)d_out;

    dim3 grid((OUTD + BX - 1) / BX,   // 12
              (OUTD + BY - 1) / BY,   // 95
              BATCH);                 // 32
    dct_conv_kernel<<<grid, NT>>>(X, out);
}

// round 10
// speedup vs baseline: 1.1029x; 1.0137x over previous
#include <cuda_runtime.h>
#include <cuda_bf16.h>

#define BX    32
#define BY    4
#define TX    38            // BX + 6
#define TYR   10            // BY + 6
#define IND   384
#define OUTD  377
#define BATCH 32
#define NT    128

// Staging: 2 row slots x 16 chunks x (2px*12 f4 + 1 f4 pad) = 2 x 400 f4
#define CHUNK_F4 25          // 24 f4 payload (2 px) + 1 f4 pad -> stride 400B

// D[k][n] = 2*cos(pi*k*(2n+1)/14), compile-time constants -> FFMA-imm
__device__ static constexpr float DC[7][7] = {
  { 2.0f, 2.0f, 2.0f, 2.0f, 2.0f, 2.0f, 2.0f },
  { 1.9498558243636472f,  1.5636629649360596f,  0.8677674782351162f, 0.0f,
   -0.8677674782351162f, -1.5636629649360596f, -1.9498558243636472f },
  { 1.8019377358048383f,  0.4450418679126288f, -1.2469796037174672f, -2.0f,
   -1.2469796037174672f,  0.4450418679126288f,  1.8019377358048383f },
  { 1.5636629649360596f, -0.8677674782351162f, -1.9498558243636472f, 0.0f,
    1.9498558243636472f,  0.8677674782351162f, -1.5636629649360596f },
  { 1.2469796037174672f, -1.8019377358048383f, -0.4450418679126288f, 2.0f,
   -0.4450418679126288f, -1.8019377358048383f,  1.2469796037174672f },
  { 0.8677674782351162f, -1.9498558243636472f,  1.5636629649360596f, 0.0f,
   -1.5636629649360596f,  1.9498558243636472f, -0.8677674782351162f },
  { 0.4450418679126288f, -1.2469796037174672f,  1.8019377358048383f, -2.0f,
    1.8019377358048383f, -1.2469796037174672f,  0.4450418679126288f }
};

__global__ __launch_bounds__(NT, 12)
void dct_conv_kernel(const float* __restrict__ X, float* __restrict__ out)
{
    __shared__ float  Xs[TYR][TX];            // input tile
    __shared__ float  Vs[7][BY][TX];          // vertical DCT pass
    __shared__ float4 Osh4[2][16 * CHUNK_F4]; // pixel-major staging, 2 rows

    const int tid  = threadIdx.x;
    const int w    = tid >> 5;
    const int lane = tid & 31;
    const int x0   = blockIdx.x * BX;
    const int y0   = blockIdx.y * BY;
    const int b    = blockIdx.z;

    const int nvx     = min(BX, OUTD - x0);
    const int nchunks = (nvx + 1) >> 1;         // 16 or 13
    const long long ZF = (long long)BATCH * OUTD * OUTD;

    // hf base pointer for this tile (row 0), computed once
    float* const hf0 = out + ZF + (((size_t)b * OUTD + y0) * OUTD + x0) * 48;

    // ---- stage input tile (clamped; OOB values only feed invalid pixels) ----
    const float* Xb = X + (size_t)b * IND * IND;
    #pragma unroll
    for (int i = tid; i < TYR * TX; i += NT) {
        int r  = i / TX, c = i - r * TX;
        int gr = y0 + r, gc = x0 + c;
        Xs[r][c] = (gr < IND && gc < IND) ? __ldg(Xb + gr * IND + gc) : 0.0f;
    }
    __syncthreads();

    // ---- vertical pass: warp w owns tile row w; cols lane and 32+lane ----
    {
        auto vert_col = [&](int xx) {
            float x[7];
            #pragma unroll
            for (int m = 0; m < 7; m++) x[m] = Xs[w + m][xx];
            float sx[3], dx[3];
            #pragma unroll
            for (int m = 0; m < 3; m++) { sx[m] = x[m] + x[6 - m]; dx[m] = x[m] - x[6 - m]; }
            #pragma unroll
            for (int k = 0; k < 7; k++) {
                float s;
                if ((k & 1) == 0) {
                    s = DC[k][3] * x[3];
                    #pragma unroll
                    for (int m = 0; m < 3; m++) s = fmaf(DC[k][m], sx[m], s);
                } else {
                    s = DC[k][0] * dx[0];
                    s = fmaf(DC[k][1], dx[1], s);
                    s = fmaf(DC[k][2], dx[2], s);
                }
                Vs[k][w][xx] = s;
            }
        };
        vert_col(lane);
        if (lane < 6) vert_col(32 + lane);
    }
    __syncthreads();

    // ---- horizontal pass: lane = pixel; pixel-major chunked staging ----
    // chunk q = lane>>1 (2 px), r = lane&1; f4 addr = q*25 + r*12 + c
    // -> word bank = (4q + 16r + 4c) % 32 : conflict-free per 8-lane phase.
    auto horiz = [&](int row, int slot) {
        float4* dst = &Osh4[slot][(lane >> 1) * CHUNK_F4 + (lane & 1) * 12];
        float b0 = 0.f, b1 = 0.f, b2 = 0.f;
        #pragma unroll
        for (int k = 0; k < 7; k++) {
            float v[7];
            #pragma unroll
            for (int n = 0; n < 7; n++) v[n] = Vs[k][row][lane + n];
            float sv[3], dv[3];
            #pragma unroll
            for (int n = 0; n < 3; n++) { sv[n] = v[n] + v[6 - n]; dv[n] = v[n] - v[6 - n]; }

            #pragma unroll
            for (int i = 0; i < 7; i++) {
                float a;
                if ((i & 1) == 0) {
                    a = DC[i][3] * v[3];
                    #pragma unroll
                    for (int n = 0; n < 3; n++) a = fmaf(DC[i][n], sv[n], a);
                } else {
                    a = DC[i][0] * dv[0];
                    a = fmaf(DC[i][1], dv[1], a);
                    a = fmaf(DC[i][2], dv[2], a);
                }

                const int ch = k * 7 + i;            // compile-time constant
                if (ch == 0) {
                    int x = x0 + lane, y = y0 + row;
                    if (x < OUTD && y < OUTD)
                        __stcs(&out[((size_t)b * OUTD + y) * OUTD + x], a);
                } else {
                    const int pos = (ch - 1) & 3;    // compile-time constant
                    if      (pos == 0) b0 = a;
                    else if (pos == 1) b1 = a;
                    else if (pos == 2) b2 = a;
                    else dst[(ch - 4) >> 2] = make_float4(b0, b1, b2, a);
                }
            }
        }
    };

    // ---- TMA bulk writeout of one 2-row phase (threads 0..63) ----
    // thread t: row slot rr = t>>5, chunk j = t&31. One 384B (or 192B) cmd.
    auto issue = [&](int phase) {
        if (tid < 64) {
            int rr  = tid >> 5;
            int j   = tid & 31;
            int row = phase * 2 + rr;
            if ((y0 + row) < OUTD && j < nchunks) {
                int sz = ((j == nchunks - 1) && (nvx & 1)) ? 192 : 384;
                const float* gp = hf0 + row * (OUTD * 48) + j * 96;
                unsigned long long gaddr =
                    (unsigned long long)__cvta_generic_to_global((void*)gp);
                unsigned int saddr = (unsigned int)__cvta_generic_to_shared(
                    &Osh4[rr][j * CHUNK_F4]);
                asm volatile("fence.proxy.async.shared::cta;" ::: "memory");
                asm volatile(
                    "cp.async.bulk.global.shared::cta.bulk_group [%0], [%1], %2;"
                    :: "l"(gaddr), "r"(saddr), "r"(sz) : "memory");
                asm volatile("cp.async.bulk.commit_group;" ::: "memory");
            }
        }
    };

    // phase 0: warps 0,1 compute+stage rows 0,1 (row = w, slot = w)
    if (w < 2) horiz(w, w);
    __syncthreads();
    issue(0);
    // wait only for the bulk engine to finish READING smem, then reuse it
    if (tid < 64)
        asm volatile("cp.async.bulk.wait_group.read 0;" ::: "memory");
    __syncthreads();

    // phase 1: warps 2,3 compute+stage rows 2,3 (row = w, slot = w-2)
    if (w >= 2) horiz(w, w - 2);
    __syncthreads();
    issue(1);
    if (tid < 64)
        asm volatile("cp.async.bulk.wait_group.read 0;" ::: "memory");
}

extern "C" void kernel_launch(void* const* d_in, const int* in_sizes, int n_in,
                              void* d_out, int out_size)
{
    const float* X = (const float*)d_in[0];
    float* out = (float*)d_out;

    dim3 grid((OUTD + BX - 1) / BX,   // 12
              (OUTD + BY - 1) / BY,   // 95
              BATCH);                 // 32
    dct_conv_kernel<<<grid, NT>>>(X, out);
}

// round 11
// speedup vs baseline: 1.1055x; 1.0023x over previous
#include <cuda_runtime.h>
#include <cuda_bf16.h>

#define BX    32
#define BY    4              // one warp per output row
#define IND   384
#define OUTD  377
#define BATCH 32
#define NT    128
#define CHUNK_F4 25          // 24 f4 payload (2 px) + 1 f4 pad -> 400B stride

// D[k][n] = 2*cos(pi*k*(2n+1)/14), compile-time constants -> FFMA-imm
__device__ static constexpr float DC[7][7] = {
  { 2.0f, 2.0f, 2.0f, 2.0f, 2.0f, 2.0f, 2.0f },
  { 1.9498558243636472f,  1.5636629649360596f,  0.8677674782351162f, 0.0f,
   -0.8677674782351162f, -1.5636629649360596f, -1.9498558243636472f },
  { 1.8019377358048383f,  0.4450418679126288f, -1.2469796037174672f, -2.0f,
   -1.2469796037174672f,  0.4450418679126288f,  1.8019377358048383f },
  { 1.5636629649360596f, -0.8677674782351162f, -1.9498558243636472f, 0.0f,
    1.9498558243636472f,  0.8677674782351162f, -1.5636629649360596f },
  { 1.2469796037174672f, -1.8019377358048383f, -0.4450418679126288f, 2.0f,
   -0.4450418679126288f, -1.8019377358048383f,  1.2469796037174672f },
  { 0.8677674782351162f, -1.9498558243636472f,  1.5636629649360596f, 0.0f,
   -1.5636629649360596f,  1.9498558243636472f, -0.8677674782351162f },
  { 0.4450418679126288f, -1.2469796037174672f,  1.8019377358048383f, -2.0f,
    1.8019377358048383f, -1.2469796037174672f,  0.4450418679126288f }
};

__device__ __forceinline__ void vert7(const float x[7], float Vk[7])
{
    float sx[3], dx[3];
    #pragma unroll
    for (int m = 0; m < 3; m++) { sx[m] = x[m] + x[6 - m]; dx[m] = x[m] - x[6 - m]; }
    #pragma unroll
    for (int k = 0; k < 7; k++) {
        float s;
        if ((k & 1) == 0) {
            s = DC[k][3] * x[3];
            #pragma unroll
            for (int m = 0; m < 3; m++) s = fmaf(DC[k][m], sx[m], s);
        } else {
            s = DC[k][0] * dx[0];
            s = fmaf(DC[k][1], dx[1], s);
            s = fmaf(DC[k][2], dx[2], s);
        }
        Vk[k] = s;
    }
}

__global__ __launch_bounds__(NT)
void dct_conv_kernel(const float* __restrict__ X, float* __restrict__ out)
{
    __shared__ float  Vs[BY][7][40];           // warp-private vertical results
    __shared__ float4 Osh4[BY][16 * CHUNK_F4]; // warp-private staging (1 row)

    const int tid  = threadIdx.x;
    const int w    = tid >> 5;          // warp = output row within tile
    const int lane = tid & 31;
    const int x0   = blockIdx.x * BX;
    const int y0   = blockIdx.y * BY;
    const int b    = blockIdx.z;

    const int nvx     = min(BX, OUTD - x0);
    const int nchunks = (nvx + 1) >> 1;          // 16 or 13
    const long long ZF = (long long)BATCH * OUTD * OUTD;
    const bool row_ok = (y0 + w) < OUTD;

    // ---- warp-private load + vertical DCT (no smem staging of input) ----
    {
        const float* Xb  = X + (size_t)b * IND * IND;
        const int gy     = y0 + w;
        const int gx0    = x0 + lane;            // always < IND
        const int gx1    = x0 + 32 + lane;       // halo cols (lanes 0..5)
        const bool ok1   = (lane < 6) && (gx1 < IND);
        float c0[7], c1[7];
        #pragma unroll
        for (int m = 0; m < 7; m++) {
            int  gr = gy + m;
            bool rv = gr < IND;
            const float* rowp = Xb + (size_t)gr * IND;
            c0[m] = rv          ? __ldg(rowp + gx0) : 0.0f;
            c1[m] = (rv && ok1) ? __ldg(rowp + gx1) : 0.0f;
        }
        float V0[7], V1[7];
        vert7(c0, V0);
        vert7(c1, V1);
        #pragma unroll
        for (int k = 0; k < 7; k++) {
            Vs[w][k][lane] = V0[k];
            if (lane < 6) Vs[w][k][32 + lane] = V1[k];
        }
    }
    __syncwarp();

    // ---- horizontal pass: lane = pixel; pixel-major chunked staging ----
    // f4 addr = (lane>>1)*25 + (lane&1)*12 + c -> banks (4q+16r+4c)%32:
    // conflict-free per 8-lane phase.
    {
        float4* dst = &Osh4[w][(lane >> 1) * CHUNK_F4 + (lane & 1) * 12];
        float b0 = 0.f, b1 = 0.f, b2 = 0.f;
        #pragma unroll
        for (int k = 0; k < 7; k++) {
            float v[7];
            #pragma unroll
            for (int n = 0; n < 7; n++) v[n] = Vs[w][k][lane + n];
            float sv[3], dv[3];
            #pragma unroll
            for (int n = 0; n < 3; n++) { sv[n] = v[n] + v[6 - n]; dv[n] = v[n] - v[6 - n]; }

            #pragma unroll
            for (int i = 0; i < 7; i++) {
                float a;
                if ((i & 1) == 0) {
                    a = DC[i][3] * v[3];
                    #pragma unroll
                    for (int n = 0; n < 3; n++) a = fmaf(DC[i][n], sv[n], a);
                } else {
                    a = DC[i][0] * dv[0];
                    a = fmaf(DC[i][1], dv[1], a);
                    a = fmaf(DC[i][2], dv[2], a);
                }

                const int ch = k * 7 + i;            // compile-time constant
                if (ch == 0) {
                    int x = x0 + lane;
                    if (x < OUTD && row_ok)
                        __stcs(&out[((size_t)b * OUTD + (y0 + w)) * OUTD + x], a);
                } else {
                    const int pos = (ch - 1) & 3;    // compile-time constant
                    if      (pos == 0) b0 = a;
                    else if (pos == 1) b1 = a;
                    else if (pos == 2) b2 = a;
                    else dst[(ch - 4) >> 2] = make_float4(b0, b1, b2, a);
                }
            }
        }
    }
    __syncwarp();

    // ---- immediate per-warp TMA bulk writeout: lane j handles chunk j ----
    if (row_ok && lane < nchunks) {
        int sz = ((lane == nchunks - 1) && (nvx & 1)) ? 192 : 384;
        const float* gp = out + ZF +
            (((size_t)b * OUTD + (y0 + w)) * OUTD + x0 + 2 * lane) * 48;
        unsigned long long gaddr =
            (unsigned long long)__cvta_generic_to_global((void*)gp);
        unsigned int saddr = (unsigned int)__cvta_generic_to_shared(
            &Osh4[w][lane * CHUNK_F4]);
        asm volatile("fence.proxy.async.shared::cta;" ::: "memory");
        asm volatile(
            "cp.async.bulk.global.shared::cta.bulk_group [%0], [%1], %2;"
            :: "l"(gaddr), "r"(saddr), "r"(sz) : "memory");
        asm volatile("cp.async.bulk.commit_group;" ::: "memory");
    }

    // ---- single tail wait (bulk groups must complete before CTA exit) ----
    asm volatile("cp.async.bulk.wait_group 0;" ::: "memory");
}

extern "C" void kernel_launch(void* const* d_in, const int* in_sizes, int n_in,
                              void* d_out, int out_size)
{
    const float* X = (const float*)d_in[0];
    float* out = (float*)d_out;

    dim3 grid((OUTD + BX - 1) / BX,   // 12
              (OUTD + BY - 1) / BY,   // 95
              BATCH);                 // 32
    dct_conv_kernel<<<grid, NT>>>(X, out);
}